// round 4
// baseline (speedup 1.0000x reference)
#include <cuda_runtime.h>

#define NPTS 2000000
#define NG   16384

typedef unsigned long long u64;

// Scratch (device globals: allocation-free, graph-capturable)
__device__ float g_xe[NPTS * 5];        // per-point embedding
__device__ float g_aggr[NG * 5];        // segment sum of xe
__device__ float g_glob[NG * 4];        // global features
__device__ float g_pooled[NG * 32];     // segment sum of xo
__device__ int   g_segstart[NG + 1];    // segment boundaries (batch is sorted)

// Weights in constant memory (uniform-const port, off the L1 path)
__constant__ u64   cWe1[60];    // [3][40]
__constant__ float cWe2[200];   // [40][5] (float view for transposed-pair builds)
__constant__ u64   cWg1[100];   // [5][40]
__constant__ u64   cWg2[80];    // [40][4]
__constant__ u64   cWo1[180];   // [9][40]
__constant__ u64   cWo2[640];   // [40][32]
__constant__ u64   cWd1[640];   // [32][40]
__constant__ u64   cWd2[20];    // [40][1]

// ---------- packed f32x2 helpers ----------
__device__ __forceinline__ u64 pk2(float lo, float hi) {
    u64 r; asm("mov.b64 %0, {%1, %2};" : "=l"(r) : "f"(lo), "f"(hi)); return r;
}
__device__ __forceinline__ void up2(u64 v, float& lo, float& hi) {
    asm("mov.b64 {%0, %1}, %2;" : "=f"(lo), "=f"(hi) : "l"(v));
}
__device__ __forceinline__ u64 ffma2(u64 a, u64 b, u64 c) {
    u64 d; asm("fma.rn.f32x2 %0, %1, %2, %3;" : "=l"(d) : "l"(a), "l"(b), "l"(c)); return d;
}
__device__ __forceinline__ u64 add2(u64 a, u64 b) {
    u64 d; asm("add.rn.f32x2 %0, %1, %2;" : "=l"(d) : "l"(a), "l"(b)); return d;
}
// leaky_relu(x, 0.01) == max(x, 0.01x) exactly (slope in (0,1))
__device__ __forceinline__ float lrelu(float v) { return fmaxf(v, 0.01f * v); }

// =====================================================================
// Pass 0: segment boundaries from sorted batch
// =====================================================================
__global__ void __launch_bounds__(256) k_bounds(const int* __restrict__ batch) {
    int i = blockIdx.x * 256 + threadIdx.x;
    if (i >= NPTS) return;
    int b0 = batch[i];
    int b1 = (i + 1 < NPTS) ? batch[i + 1] : NG;
    if (i == 0)
        for (int b = 0; b <= b0; b++) g_segstart[b] = 0;
    for (int b = b0 + 1; b <= b1; b++) g_segstart[b] = i + 1;
}

// =====================================================================
// Pass 1: xe = ffn(x, We1, We2); store xe; exact per-graph sum -> g_aggr
// One block (64 threads) per graph.
// =====================================================================
__global__ void __launch_bounds__(64, 8) k_emb(const float* __restrict__ x) {
    int g = blockIdx.x;
    int s = g_segstart[g], e = g_segstart[g + 1];
    int tid = threadIdx.x, lane = tid & 31, wid = tid >> 5;

    float acc[5] = {0.f, 0.f, 0.f, 0.f, 0.f};

    for (int base = s; base < e; base += 64) {
        int i = base + tid;
        if (i < e) {
            float in3[3] = {x[3 * i + 0], x[3 * i + 1], x[3 * i + 2]};

            // hidden 3 -> 40 (packed)
            u64 h[20];
#pragma unroll
            for (int q = 0; q < 20; q++) h[q] = 0ULL;
#pragma unroll
            for (int k = 0; k < 3; k++) {
                u64 a = pk2(in3[k], in3[k]);
#pragma unroll
                for (int q = 0; q < 20; q++) h[q] = ffma2(a, cWe1[k * 20 + q], h[q]);
            }
#pragma unroll
            for (int q = 0; q < 20; q++) {
                float lo, hi; up2(h[q], lo, hi);
                h[q] = pk2(lrelu(lo), lrelu(hi));
            }

            // out 40 -> 5: dot over packed hidden pairs; weight pairs built from
            // scalar constants (loop-invariant -> hoisted by ptxas where regs allow)
            float xe[5];
#pragma unroll
            for (int j = 0; j < 5; j++) {
                u64 a = 0ULL;
#pragma unroll
                for (int q = 0; q < 20; q++) {
                    u64 w = pk2(cWe2[(2 * q) * 5 + j], cWe2[(2 * q + 1) * 5 + j]);
                    a = ffma2(h[q], w, a);
                }
                float lo, hi; up2(a, lo, hi);
                xe[j] = lrelu(lo + hi);
            }
#pragma unroll
            for (int j = 0; j < 5; j++) {
                g_xe[i * 5 + j] = xe[j];
                acc[j] += xe[j];
            }
        }
    }

    // block reduce 5 floats (all 32 lanes active; inactive-point lanes hold 0)
#pragma unroll
    for (int j = 0; j < 5; j++)
#pragma unroll
        for (int d = 16; d >= 1; d >>= 1)
            acc[j] += __shfl_down_sync(0xffffffffu, acc[j], d);

    __shared__ float sred[2][5];
    if (lane == 0)
#pragma unroll
        for (int j = 0; j < 5; j++) sred[wid][j] = acc[j];
    __syncthreads();
    if (tid < 5) g_aggr[g * 5 + tid] = sred[0][tid] + sred[1][tid];
}

// =====================================================================
// Pass 2: x_global = ffn(x_aggr, Wg1, Wg2)
// =====================================================================
__global__ void __launch_bounds__(256) k_glob() {
    int g = blockIdx.x * 256 + threadIdx.x;   // grid = NG/256 exactly

    float in5[5];
#pragma unroll
    for (int j = 0; j < 5; j++) in5[j] = g_aggr[g * 5 + j];

    u64 acc[20];
#pragma unroll
    for (int j = 0; j < 20; j++) acc[j] = 0ULL;
#pragma unroll
    for (int k = 0; k < 5; k++) {
        u64 a = pk2(in5[k], in5[k]);
#pragma unroll
        for (int q = 0; q < 20; q++) acc[q] = ffma2(a, cWg1[k * 20 + q], acc[q]);
    }
    float hf[40];
#pragma unroll
    for (int j = 0; j < 20; j++) {
        float lo, hi; up2(acc[j], lo, hi);
        hf[2 * j] = lrelu(lo); hf[2 * j + 1] = lrelu(hi);
    }
    u64 o01 = 0ULL, o23 = 0ULL;
#pragma unroll
    for (int k = 0; k < 40; k++) {
        u64 a = pk2(hf[k], hf[k]);
        o01 = ffma2(a, cWg2[k * 2 + 0], o01);
        o23 = ffma2(a, cWg2[k * 2 + 1], o23);
    }
    float o0, o1, o2, o3;
    up2(o01, o0, o1); up2(o23, o2, o3);
    ((float4*)g_glob)[g] = make_float4(lrelu(o0), lrelu(o1), lrelu(o2), lrelu(o3));
}

// =====================================================================
// Pass 3: xo = ffn([xe, xg], Wo1, Wo2); exact per-graph sum -> g_pooled
// One block (64 threads) per graph; register accumulators, no atomics.
// =====================================================================
__global__ void __launch_bounds__(64, 8) k_out() {
    int g = blockIdx.x;
    int s = g_segstart[g], e = g_segstart[g + 1];
    int tid = threadIdx.x, lane = tid & 31, wid = tid >> 5;

    float4 xg = ((const float4*)g_glob)[g];   // one graph per block: load once

    u64 acc[16];   // packed running sums of the 32 output components
#pragma unroll
    for (int q = 0; q < 16; q++) acc[q] = 0ULL;

    for (int base = s; base < e; base += 64) {
        int i = base + tid;
        if (i < e) {
            float in9[9];
            const float* xp = g_xe + i * 5;
#pragma unroll
            for (int j = 0; j < 5; j++) in9[j] = xp[j];
            in9[5] = xg.x; in9[6] = xg.y; in9[7] = xg.z; in9[8] = xg.w;

            // hidden 9 -> 40
            u64 h[20];
#pragma unroll
            for (int q = 0; q < 20; q++) h[q] = 0ULL;
#pragma unroll
            for (int k = 0; k < 9; k++) {
                u64 a = pk2(in9[k], in9[k]);
#pragma unroll
                for (int q = 0; q < 20; q++) h[q] = ffma2(a, cWo1[k * 20 + q], h[q]);
            }
#pragma unroll
            for (int q = 0; q < 20; q++) {
                float lo, hi; up2(h[q], lo, hi);
                h[q] = pk2(lrelu(lo), lrelu(hi));
            }

            // out 40 -> 32 in two halves of 16; activation then packed accumulate
#pragma unroll
            for (int hf = 0; hf < 2; hf++) {
                u64 o[8];
#pragma unroll
                for (int q = 0; q < 8; q++) o[q] = 0ULL;
#pragma unroll
                for (int j = 0; j < 20; j++) {
                    float a0, a1; up2(h[j], a0, a1);
                    u64 p0 = pk2(a0, a0), p1 = pk2(a1, a1);
#pragma unroll
                    for (int q = 0; q < 8; q++)
                        o[q] = ffma2(p0, cWo2[(2 * j) * 16 + hf * 8 + q], o[q]);
#pragma unroll
                    for (int q = 0; q < 8; q++)
                        o[q] = ffma2(p1, cWo2[(2 * j + 1) * 16 + hf * 8 + q], o[q]);
                }
#pragma unroll
                for (int q = 0; q < 8; q++) {
                    float lo, hi; up2(o[q], lo, hi);
                    acc[hf * 8 + q] = add2(acc[hf * 8 + q], pk2(lrelu(lo), lrelu(hi)));
                }
            }
        }
    }

    // warp reduce 16 packed sums (all lanes active; empty lanes hold 0)
    float alo[16], ahi[16];
#pragma unroll
    for (int q = 0; q < 16; q++) up2(acc[q], alo[q], ahi[q]);
#pragma unroll
    for (int q = 0; q < 16; q++)
#pragma unroll
        for (int d = 16; d >= 1; d >>= 1) {
            alo[q] += __shfl_down_sync(0xffffffffu, alo[q], d);
            ahi[q] += __shfl_down_sync(0xffffffffu, ahi[q], d);
        }

    __shared__ float sred[2][32];
    if (lane == 0)
#pragma unroll
        for (int q = 0; q < 16; q++) {
            sred[wid][2 * q]     = alo[q];
            sred[wid][2 * q + 1] = ahi[q];
        }
    __syncthreads();
    if (tid < 32) g_pooled[g * 32 + tid] = sred[0][tid] + sred[1][tid];
}

// =====================================================================
// Pass 4: out = ffn(pooled, Wd1, Wd2, final_linear=True)
// =====================================================================
__global__ void __launch_bounds__(256) k_disc(float* __restrict__ out) {
    int g = blockIdx.x * 256 + threadIdx.x;   // grid = NG/256 exactly
    float p[32];
#pragma unroll
    for (int j = 0; j < 32; j++) p[j] = g_pooled[g * 32 + j];

    u64 acc[20];
#pragma unroll
    for (int j = 0; j < 20; j++) acc[j] = 0ULL;
#pragma unroll
    for (int k = 0; k < 32; k++) {
        u64 a = pk2(p[k], p[k]);
#pragma unroll
        for (int q = 0; q < 20; q++) acc[q] = ffma2(a, cWd1[k * 20 + q], acc[q]);
    }
    u64 s = 0ULL;
#pragma unroll
    for (int j = 0; j < 20; j++) {
        float lo, hi; up2(acc[j], lo, hi);
        s = ffma2(pk2(lrelu(lo), lrelu(hi)), cWd2[j], s);
    }
    float lo, hi; up2(s, lo, hi);
    out[g] = lo + hi;   // final_linear: no activation
}

extern "C" void kernel_launch(void* const* d_in, const int* in_sizes, int n_in,
                              void* d_out, int out_size) {
    const float* x     = (const float*)d_in[0];
    const int*   batch = (const int*)d_in[1];
    float* out = (float*)d_out;

    // Stage weights into constant memory (async D2D: graph-capturable)
    cudaMemcpyToSymbolAsync(cWe1, d_in[2],  120 * 4, 0, cudaMemcpyDeviceToDevice, 0);
    cudaMemcpyToSymbolAsync(cWe2, d_in[3],  200 * 4, 0, cudaMemcpyDeviceToDevice, 0);
    cudaMemcpyToSymbolAsync(cWg1, d_in[4],  200 * 4, 0, cudaMemcpyDeviceToDevice, 0);
    cudaMemcpyToSymbolAsync(cWg2, d_in[5],  160 * 4, 0, cudaMemcpyDeviceToDevice, 0);
    cudaMemcpyToSymbolAsync(cWo1, d_in[6],  360 * 4, 0, cudaMemcpyDeviceToDevice, 0);
    cudaMemcpyToSymbolAsync(cWo2, d_in[7], 1280 * 4, 0, cudaMemcpyDeviceToDevice, 0);
    cudaMemcpyToSymbolAsync(cWd1, d_in[8], 1280 * 4, 0, cudaMemcpyDeviceToDevice, 0);
    cudaMemcpyToSymbolAsync(cWd2, d_in[9],   40 * 4, 0, cudaMemcpyDeviceToDevice, 0);

    k_bounds<<<(NPTS + 255) / 256, 256>>>(batch);
    k_emb<<<NG, 64>>>(x);
    k_glob<<<NG / 256, 256>>>();
    k_out<<<NG, 64>>>();
    k_disc<<<NG / 256, 256>>>(out);
}

// round 5
// speedup vs baseline: 1.1488x; 1.1488x over previous
#include <cuda_runtime.h>

#define NPTS 2000000
#define NG   16384

typedef unsigned long long u64;

// Scratch (device globals: allocation-free, graph-capturable)
__device__ float g_xe[NPTS * 5];        // per-point embedding
__device__ float g_aggr[NG * 5];        // segment sum of xe
__device__ float g_glob[NG * 4];        // global features
__device__ float g_pooled[NG * 32];     // segment sum of xo
__device__ u64   g_We2t_dev[100];       // prep output: We2 transposed packed
__device__ u64   g_Wo2t_dev[640];       // prep output: Wo2 transposed packed

// Weights in constant memory (uniform-const port, off the L1 path)
__constant__ u64 cWe1[60];     // [3][40] packed over outputs
__constant__ u64 cWe2t[100];   // transposed: [5 outputs][20 hidden-pairs]
__constant__ u64 cWg1[100];    // [5][40]
__constant__ u64 cWg2[80];     // [40][4]
__constant__ u64 cWo1[180];    // [9][40]
__constant__ u64 cWo2t[640];   // transposed: [32 outputs][20 hidden-pairs]
__constant__ u64 cWd1[640];    // [32][40]
__constant__ u64 cWd2[20];     // [40][1]

// ---------- packed f32x2 helpers ----------
__device__ __forceinline__ u64 pk2(float lo, float hi) {
    u64 r; asm("mov.b64 %0, {%1, %2};" : "=l"(r) : "f"(lo), "f"(hi)); return r;
}
__device__ __forceinline__ void up2(u64 v, float& lo, float& hi) {
    asm("mov.b64 {%0, %1}, %2;" : "=f"(lo), "=f"(hi) : "l"(v));
}
__device__ __forceinline__ u64 ffma2(u64 a, u64 b, u64 c) {
    u64 d; asm("fma.rn.f32x2 %0, %1, %2, %3;" : "=l"(d) : "l"(a), "l"(b), "l"(c)); return d;
}
__device__ __forceinline__ u64 mul2(u64 a, u64 b) {
    u64 d; asm("mul.rn.f32x2 %0, %1, %2;" : "=l"(d) : "l"(a), "l"(b)); return d;
}
// scalar leaky_relu (exact)
__device__ __forceinline__ float lrelu(float v) { return fmaxf(v, 0.01f * v); }
// packed leaky_relu: 0.505x + 0.495|x|  (== lrelu to ~6e-6 rel, no unpack needed)
__device__ __forceinline__ u64 plrelu2(u64 v) {
    const float A = 0.505f, B = 0.495f;
    u64 cA = pk2(A, A), cB = pk2(B, B);
    u64 av = v & 0x7FFFFFFF7FFFFFFFULL;
    return ffma2(av, cB, mul2(v, cA));
}

// ---------- prep: build transposed packed layer-2 weights ----------
__global__ void __launch_bounds__(128) k_prep(const float* __restrict__ We2,   // [40][5]
                                              const float* __restrict__ Wo2) { // [40][32]
    int t = threadIdx.x;
    if (t < 100) {
        int j = t / 20, q = t % 20;
        g_We2t_dev[t] = pk2(We2[(2 * q) * 5 + j], We2[(2 * q + 1) * 5 + j]);
    }
    for (int s = t; s < 640; s += 128) {
        int j = s / 20, q = s % 20;
        g_Wo2t_dev[s] = pk2(Wo2[(2 * q) * 32 + j], Wo2[(2 * q + 1) * 32 + j]);
    }
}

// ---------- zero g_aggr (g_pooled is zeroed inside k_glob) ----------
__global__ void __launch_bounds__(256) k_zero() {
    int i = blockIdx.x * 256 + threadIdx.x;
    if (i < NG * 5 / 4) ((float4*)g_aggr)[i] = make_float4(0.f, 0.f, 0.f, 0.f);
}

// =====================================================================
// Pass 1: xe = ffn(x, We1, We2); store xe; segment-sum -> g_aggr.  P=2.
// =====================================================================
__global__ void __launch_bounds__(256, 2) k_emb(const float* __restrict__ x,
                                                const int* __restrict__ batch) {
    int tid = threadIdx.x;
    int t = blockIdx.x * 256 + tid;
    int i0 = t * 2;
    if (i0 >= NPTS) return;   // NPTS % 64 == 0 -> surviving warps are full

    const float2* xp = (const float2*)(x + i0 * 3);
    float2 p0 = xp[0], p1 = xp[1], p2 = xp[2];
    float inA[3] = {p0.x, p0.y, p1.x};
    float inB[3] = {p1.y, p2.x, p2.y};

    // hidden 3 -> 40 (packed over outputs)
    u64 hA[20], hB[20];
#pragma unroll
    for (int q = 0; q < 20; q++) { hA[q] = 0ULL; hB[q] = 0ULL; }
#pragma unroll
    for (int k = 0; k < 3; k++) {
        u64 aA = pk2(inA[k], inA[k]);
        u64 aB = pk2(inB[k], inB[k]);
#pragma unroll
        for (int q = 0; q < 20; q++) {
            u64 w = cWe1[k * 20 + q];
            hA[q] = ffma2(aA, w, hA[q]);
            hB[q] = ffma2(aB, w, hB[q]);
        }
    }
#pragma unroll
    for (int q = 0; q < 20; q++) { hA[q] = plrelu2(hA[q]); hB[q] = plrelu2(hB[q]); }

    // out 40 -> 5: packed dot over hidden pairs (transposed weights)
    float xeA[5], xeB[5];
#pragma unroll
    for (int j = 0; j < 5; j++) {
        u64 aA = 0ULL, aB = 0ULL;
#pragma unroll
        for (int q = 0; q < 20; q++) {
            u64 w = cWe2t[j * 20 + q];
            aA = ffma2(hA[q], w, aA);
            aB = ffma2(hB[q], w, aB);
        }
        float lo, hi;
        up2(aA, lo, hi); xeA[j] = lrelu(lo + hi);
        up2(aB, lo, hi); xeB[j] = lrelu(lo + hi);
    }

    // store xe for both points: 10 consecutive floats, 8B-aligned -> 5 STG.64
    {
        float2* xo = (float2*)(g_xe + i0 * 5);
        xo[0] = make_float2(xeA[0], xeA[1]);
        xo[1] = make_float2(xeA[2], xeA[3]);
        xo[2] = make_float2(xeA[4], xeB[0]);
        xo[3] = make_float2(xeB[1], xeB[2]);
        xo[4] = make_float2(xeB[3], xeB[4]);
    }

    // segmented sum -> g_aggr
    int2 bb = *(const int2*)(batch + i0);
    int bA = bb.x, bB = bb.y;
    bool same = (bA == bB);
    unsigned peers = __match_any_sync(0xffffffffu, bA);
    int lane = tid & 31;
    int hiL = 31 - __clz(peers);
    bool leader = (lane == __ffs(peers) - 1);
#pragma unroll
    for (int c = 0; c < 5; c++) {
        float v = same ? (xeA[c] + xeB[c]) : xeA[c];
#pragma unroll
        for (int d = 1; d < 32; d <<= 1) {
            float s = __shfl_down_sync(0xffffffffu, v, d);
            if (lane + d <= hiL) v += s;
        }
        if (leader) atomicAdd(&g_aggr[bA * 5 + c], v);
        if (!same)  atomicAdd(&g_aggr[bB * 5 + c], xeB[c]);  // rare boundary leftover
    }
}

// =====================================================================
// Pass 2: x_global = ffn(x_aggr, Wg1, Wg2); also zero g_pooled
// =====================================================================
__global__ void __launch_bounds__(256) k_glob() {
    int g = blockIdx.x * 256 + threadIdx.x;   // grid = NG/256 exactly

    {   // zero g_pooled: 128K float4 over 16384 threads -> 8 each
        float4 z = make_float4(0.f, 0.f, 0.f, 0.f);
        float4* pp = (float4*)g_pooled;
#pragma unroll
        for (int r = 0; r < 8; r++) pp[g * 8 + r] = z;
    }

    float in5[5];
#pragma unroll
    for (int j = 0; j < 5; j++) in5[j] = g_aggr[g * 5 + j];

    u64 acc[20];
#pragma unroll
    for (int j = 0; j < 20; j++) acc[j] = 0ULL;
#pragma unroll
    for (int k = 0; k < 5; k++) {
        u64 a = pk2(in5[k], in5[k]);
#pragma unroll
        for (int q = 0; q < 20; q++) acc[q] = ffma2(a, cWg1[k * 20 + q], acc[q]);
    }
    float hf[40];
#pragma unroll
    for (int j = 0; j < 20; j++) {
        float lo, hi; up2(acc[j], lo, hi);
        hf[2 * j] = lrelu(lo); hf[2 * j + 1] = lrelu(hi);
    }
    u64 o01 = 0ULL, o23 = 0ULL;
#pragma unroll
    for (int k = 0; k < 40; k++) {
        u64 a = pk2(hf[k], hf[k]);
        o01 = ffma2(a, cWg2[k * 2 + 0], o01);
        o23 = ffma2(a, cWg2[k * 2 + 1], o23);
    }
    float o0, o1, o2, o3;
    up2(o01, o0, o1); up2(o23, o2, o3);
    ((float4*)g_glob)[g] = make_float4(lrelu(o0), lrelu(o1), lrelu(o2), lrelu(o3));
}

// =====================================================================
// Pass 3: xo = ffn([xe, xg], Wo1, Wo2); segment-sum -> g_pooled.  P=2.
// Layer 2 via transposed packed weights: no broadcast rebuilds.
// =====================================================================
__global__ void __launch_bounds__(256, 2) k_out(const int* __restrict__ batch) {
    int tid = threadIdx.x;
    int t = blockIdx.x * 256 + tid;
    int i0 = t * 2;
    if (i0 >= NPTS) return;

    int2 bb = *(const int2*)(batch + i0);
    int bA = bb.x, bB = bb.y;
    float4 xgA = ((const float4*)g_glob)[bA];
    float4 xgB = ((const float4*)g_glob)[bB];

    float inA[9], inB[9];
    {
        const float2* xep = (const float2*)(g_xe + i0 * 5);
        float2 e0 = xep[0], e1 = xep[1], e2 = xep[2], e3 = xep[3], e4 = xep[4];
        inA[0] = e0.x; inA[1] = e0.y; inA[2] = e1.x; inA[3] = e1.y; inA[4] = e2.x;
        inB[0] = e2.y; inB[1] = e3.x; inB[2] = e3.y; inB[3] = e4.x; inB[4] = e4.y;
        inA[5] = xgA.x; inA[6] = xgA.y; inA[7] = xgA.z; inA[8] = xgA.w;
        inB[5] = xgB.x; inB[6] = xgB.y; inB[7] = xgB.z; inB[8] = xgB.w;
    }

    // hidden 9 -> 40 (packed over outputs)
    u64 hA[20], hB[20];
#pragma unroll
    for (int q = 0; q < 20; q++) { hA[q] = 0ULL; hB[q] = 0ULL; }
#pragma unroll
    for (int k = 0; k < 9; k++) {
        u64 aA = pk2(inA[k], inA[k]);
        u64 aB = pk2(inB[k], inB[k]);
#pragma unroll
        for (int q = 0; q < 20; q++) {
            u64 w = cWo1[k * 20 + q];
            hA[q] = ffma2(aA, w, hA[q]);
            hB[q] = ffma2(aB, w, hB[q]);
        }
    }
#pragma unroll
    for (int q = 0; q < 20; q++) { hA[q] = plrelu2(hA[q]); hB[q] = plrelu2(hB[q]); }

    // segment bookkeeping (once)
    bool same = (bA == bB);
    unsigned peers = __match_any_sync(0xffffffffu, bA);
    int lane = tid & 31;
    int hiL = 31 - __clz(peers);
    bool leader = (lane == __ffs(peers) - 1);

    // out 40 -> 32: 4 groups of 8 outputs; packed dot over hidden pairs
#pragma unroll
    for (int grp = 0; grp < 4; grp++) {
        u64 oA[8], oB[8];
#pragma unroll
        for (int jj = 0; jj < 8; jj++) { oA[jj] = 0ULL; oB[jj] = 0ULL; }
#pragma unroll
        for (int q = 0; q < 20; q++) {
            u64 a = hA[q], b = hB[q];
#pragma unroll
            for (int jj = 0; jj < 8; jj++) {
                u64 w = cWo2t[(grp * 8 + jj) * 20 + q];
                oA[jj] = ffma2(a, w, oA[jj]);
                oB[jj] = ffma2(b, w, oB[jj]);
            }
        }
        // horizontal add + activation + pair-merge + segmented reduce + atomics
#pragma unroll
        for (int jj = 0; jj < 8; jj++) {
            float lo, hi;
            up2(oA[jj], lo, hi);
            float vA = lrelu(lo + hi);
            up2(oB[jj], lo, hi);
            float vB = lrelu(lo + hi);
            float v = same ? (vA + vB) : vA;
#pragma unroll
            for (int d = 1; d < 32; d <<= 1) {
                float s = __shfl_down_sync(0xffffffffu, v, d);
                if (lane + d <= hiL) v += s;
            }
            int c = grp * 8 + jj;
            if (leader) atomicAdd(&g_pooled[bA * 32 + c], v);
            if (!same)  atomicAdd(&g_pooled[bB * 32 + c], vB);
        }
    }
}

// =====================================================================
// Pass 4: out = ffn(pooled, Wd1, Wd2, final_linear=True)
// =====================================================================
__global__ void __launch_bounds__(256) k_disc(float* __restrict__ out) {
    int g = blockIdx.x * 256 + threadIdx.x;   // grid = NG/256 exactly
    float p[32];
#pragma unroll
    for (int j = 0; j < 32; j++) p[j] = g_pooled[g * 32 + j];

    u64 acc[20];
#pragma unroll
    for (int j = 0; j < 20; j++) acc[j] = 0ULL;
#pragma unroll
    for (int k = 0; k < 32; k++) {
        u64 a = pk2(p[k], p[k]);
#pragma unroll
        for (int q = 0; q < 20; q++) acc[q] = ffma2(a, cWd1[k * 20 + q], acc[q]);
    }
    u64 s = 0ULL;
#pragma unroll
    for (int j = 0; j < 20; j++) s = ffma2(plrelu2(acc[j]), cWd2[j], s);
    float lo, hi; up2(s, lo, hi);
    out[g] = lo + hi;   // final_linear: no activation
}

extern "C" void kernel_launch(void* const* d_in, const int* in_sizes, int n_in,
                              void* d_out, int out_size) {
    const float* x     = (const float*)d_in[0];
    const int*   batch = (const int*)d_in[1];
    float* out = (float*)d_out;

    // Direct-layout weights -> constant (async D2D)
    cudaMemcpyToSymbolAsync(cWe1, d_in[2],  120 * 4, 0, cudaMemcpyDeviceToDevice, 0);
    cudaMemcpyToSymbolAsync(cWg1, d_in[4],  200 * 4, 0, cudaMemcpyDeviceToDevice, 0);
    cudaMemcpyToSymbolAsync(cWg2, d_in[5],  160 * 4, 0, cudaMemcpyDeviceToDevice, 0);
    cudaMemcpyToSymbolAsync(cWo1, d_in[6],  360 * 4, 0, cudaMemcpyDeviceToDevice, 0);
    cudaMemcpyToSymbolAsync(cWd1, d_in[8], 1280 * 4, 0, cudaMemcpyDeviceToDevice, 0);
    cudaMemcpyToSymbolAsync(cWd2, d_in[9],   40 * 4, 0, cudaMemcpyDeviceToDevice, 0);

    // Transposed packed layer-2 weights: build on device, then copy to constant
    k_prep<<<1, 128>>>((const float*)d_in[3], (const float*)d_in[7]);
    void* pWe2t = nullptr; void* pWo2t = nullptr;
    cudaGetSymbolAddress(&pWe2t, g_We2t_dev);
    cudaGetSymbolAddress(&pWo2t, g_Wo2t_dev);
    cudaMemcpyToSymbolAsync(cWe2t, pWe2t, 100 * 8, 0, cudaMemcpyDeviceToDevice, 0);
    cudaMemcpyToSymbolAsync(cWo2t, pWo2t, 640 * 8, 0, cudaMemcpyDeviceToDevice, 0);

    const int nblk2 = (NPTS / 2 + 255) / 256;   // P=2 kernels
    k_zero<<<(NG * 5 / 4 + 255) / 256, 256>>>();
    k_emb<<<nblk2, 256>>>(x, batch);
    k_glob<<<NG / 256, 256>>>();
    k_out<<<nblk2, 256>>>(batch);
    k_disc<<<NG / 256, 256>>>(out);
}

// round 6
// speedup vs baseline: 1.2329x; 1.0732x over previous
#include <cuda_runtime.h>

#define NPTS 2000000
#define NG   16384

typedef unsigned long long u64;

// Scratch (device globals: allocation-free, graph-capturable)
__device__ float g_xe[NPTS * 5];        // per-point embedding
__device__ float g_aggr[NG * 5];        // segment sum of xe
__device__ float g_pooled[NG * 32];     // segment sum of xo
__device__ u64   g_hbias[NG * 20];      // per-graph W1b·xg, packed pairs
__device__ u64   g_We2t_dev[100];       // prep: We2 transposed packed
__device__ u64   g_Wo2t_dev[640];       // prep: Wo2 transposed packed

// Weights in constant memory (uniform-const port, off the L1 path)
__constant__ u64 cWe1[60];     // [3][40] packed over outputs
__constant__ u64 cWe2t[100];   // transposed: [5 outputs][20 hidden-pairs]
__constant__ u64 cWg1[100];    // [5][40]
__constant__ u64 cWg2[80];     // [40][4]
__constant__ u64 cWo1[180];    // [9][40]: rows 0-4 used by k_out, rows 5-8 by k_glob
__constant__ u64 cWo2t[640];   // transposed: [32 outputs][20 hidden-pairs]
__constant__ u64 cWd1[640];    // [32][40]
__constant__ u64 cWd2[20];     // [40][1]

// ---------- packed f32x2 helpers ----------
__device__ __forceinline__ u64 pk2(float lo, float hi) {
    u64 r; asm("mov.b64 %0, {%1, %2};" : "=l"(r) : "f"(lo), "f"(hi)); return r;
}
__device__ __forceinline__ void up2(u64 v, float& lo, float& hi) {
    asm("mov.b64 {%0, %1}, %2;" : "=f"(lo), "=f"(hi) : "l"(v));
}
__device__ __forceinline__ u64 ffma2(u64 a, u64 b, u64 c) {
    u64 d; asm("fma.rn.f32x2 %0, %1, %2, %3;" : "=l"(d) : "l"(a), "l"(b), "l"(c)); return d;
}
__device__ __forceinline__ u64 mul2(u64 a, u64 b) {
    u64 d; asm("mul.rn.f32x2 %0, %1, %2;" : "=l"(d) : "l"(a), "l"(b)); return d;
}
// scalar leaky_relu (exact)
__device__ __forceinline__ float lrelu(float v) { return fmaxf(v, 0.01f * v); }
// packed leaky_relu: 0.505x + 0.495|x| (== lrelu to ~6e-6 rel, no unpack)
__device__ __forceinline__ u64 plrelu2(u64 v) {
    u64 cA = pk2(0.505f, 0.505f), cB = pk2(0.495f, 0.495f);
    u64 av = v & 0x7FFFFFFF7FFFFFFFULL;
    return ffma2(av, cB, mul2(v, cA));
}

// ---------- pre: zero g_aggr + build transposed packed layer-2 weights ----------
__global__ void __launch_bounds__(256) k_pre(const float* __restrict__ We2,   // [40][5]
                                             const float* __restrict__ Wo2) { // [40][32]
    int i = blockIdx.x * 256 + threadIdx.x;
    if (i < NG * 5 / 4) ((float4*)g_aggr)[i] = make_float4(0.f, 0.f, 0.f, 0.f);
    if (i < 100) {
        int j = i / 20, q = i % 20;
        g_We2t_dev[i] = pk2(We2[(2 * q) * 5 + j], We2[(2 * q + 1) * 5 + j]);
    }
    if (i < 640) {
        int j = i / 20, q = i % 20;
        g_Wo2t_dev[i] = pk2(Wo2[(2 * q) * 32 + j], Wo2[(2 * q + 1) * 32 + j]);
    }
}

// =====================================================================
// Pass 1: xe = ffn(x, We1, We2); store xe; segment-sum -> g_aggr.  P=2.
// =====================================================================
__global__ void __launch_bounds__(256, 2) k_emb(const float* __restrict__ x,
                                                const int* __restrict__ batch) {
    int tid = threadIdx.x;
    int t = blockIdx.x * 256 + tid;
    int i0 = t * 2;
    if (i0 >= NPTS) return;   // NPTS % 64 == 0 -> surviving warps are full

    const float2* xp = (const float2*)(x + i0 * 3);
    float2 p0 = xp[0], p1 = xp[1], p2 = xp[2];
    float inA[3] = {p0.x, p0.y, p1.x};
    float inB[3] = {p1.y, p2.x, p2.y};

    // hidden 3 -> 40 (packed over outputs)
    u64 hA[20], hB[20];
#pragma unroll
    for (int q = 0; q < 20; q++) { hA[q] = 0ULL; hB[q] = 0ULL; }
#pragma unroll
    for (int k = 0; k < 3; k++) {
        u64 aA = pk2(inA[k], inA[k]);
        u64 aB = pk2(inB[k], inB[k]);
#pragma unroll
        for (int q = 0; q < 20; q++) {
            u64 w = cWe1[k * 20 + q];
            hA[q] = ffma2(aA, w, hA[q]);
            hB[q] = ffma2(aB, w, hB[q]);
        }
    }
#pragma unroll
    for (int q = 0; q < 20; q++) { hA[q] = plrelu2(hA[q]); hB[q] = plrelu2(hB[q]); }

    // out 40 -> 5: packed dot over hidden pairs (transposed weights)
    float xeA[5], xeB[5];
#pragma unroll
    for (int j = 0; j < 5; j++) {
        u64 aA = 0ULL, aB = 0ULL;
#pragma unroll
        for (int q = 0; q < 20; q++) {
            u64 w = cWe2t[j * 20 + q];
            aA = ffma2(hA[q], w, aA);
            aB = ffma2(hB[q], w, aB);
        }
        float lo, hi;
        up2(aA, lo, hi); xeA[j] = lrelu(lo + hi);
        up2(aB, lo, hi); xeB[j] = lrelu(lo + hi);
    }

    // store xe for both points: 10 consecutive floats -> 5 STG.64
    {
        float2* xo = (float2*)(g_xe + i0 * 5);
        xo[0] = make_float2(xeA[0], xeA[1]);
        xo[1] = make_float2(xeA[2], xeA[3]);
        xo[2] = make_float2(xeA[4], xeB[0]);
        xo[3] = make_float2(xeB[1], xeB[2]);
        xo[4] = make_float2(xeB[3], xeB[4]);
    }

    // segmented sum -> g_aggr
    int2 bb = *(const int2*)(batch + i0);
    int bA = bb.x, bB = bb.y;
    bool same = (bA == bB);
    unsigned peers = __match_any_sync(0xffffffffu, bA);
    int lane = tid & 31;
    int hiL = 31 - __clz(peers);
    bool leader = (lane == __ffs(peers) - 1);
#pragma unroll
    for (int c = 0; c < 5; c++) {
        float v = same ? (xeA[c] + xeB[c]) : xeA[c];
#pragma unroll
        for (int d = 1; d < 32; d <<= 1) {
            float s = __shfl_down_sync(0xffffffffu, v, d);
            if (lane + d <= hiL) v += s;
        }
        if (leader) atomicAdd(&g_aggr[bA * 5 + c], v);
        if (!same)  atomicAdd(&g_aggr[bB * 5 + c], xeB[c]);  // rare boundary leftover
    }
}

// =====================================================================
// Pass 2: xg = ffn(x_aggr, Wg1, Wg2); hbias = W1b·xg (packed) -> g_hbias.
// Also zeroes g_pooled.
// =====================================================================
__global__ void __launch_bounds__(256) k_glob() {
    int g = blockIdx.x * 256 + threadIdx.x;   // grid = NG/256 exactly

    {   // zero g_pooled: 128K float4 over 16384 threads -> 8 each
        float4 z = make_float4(0.f, 0.f, 0.f, 0.f);
        float4* pp = (float4*)g_pooled;
#pragma unroll
        for (int r = 0; r < 8; r++) pp[g * 8 + r] = z;
    }

    float in5[5];
#pragma unroll
    for (int j = 0; j < 5; j++) in5[j] = g_aggr[g * 5 + j];

    u64 acc[20];
#pragma unroll
    for (int j = 0; j < 20; j++) acc[j] = 0ULL;
#pragma unroll
    for (int k = 0; k < 5; k++) {
        u64 a = pk2(in5[k], in5[k]);
#pragma unroll
        for (int q = 0; q < 20; q++) acc[q] = ffma2(a, cWg1[k * 20 + q], acc[q]);
    }
    float hf[40];
#pragma unroll
    for (int j = 0; j < 20; j++) {
        float lo, hi; up2(acc[j], lo, hi);
        hf[2 * j] = lrelu(lo); hf[2 * j + 1] = lrelu(hi);
    }
    u64 o01 = 0ULL, o23 = 0ULL;
#pragma unroll
    for (int k = 0; k < 40; k++) {
        u64 a = pk2(hf[k], hf[k]);
        o01 = ffma2(a, cWg2[k * 2 + 0], o01);
        o23 = ffma2(a, cWg2[k * 2 + 1], o23);
    }
    float o0, o1, o2, o3;
    up2(o01, o0, o1); up2(o23, o2, o3);
    float xg[4] = {lrelu(o0), lrelu(o1), lrelu(o2), lrelu(o3)};

    // hbias = W1b·xg over Wo1 rows 5..8 (packed pairs) -> per-graph constant
    u64 hb[20];
#pragma unroll
    for (int q = 0; q < 20; q++) hb[q] = 0ULL;
#pragma unroll
    for (int k = 0; k < 4; k++) {
        u64 a = pk2(xg[k], xg[k]);
#pragma unroll
        for (int q = 0; q < 20; q++) hb[q] = ffma2(a, cWo1[(5 + k) * 20 + q], hb[q]);
    }
#pragma unroll
    for (int q = 0; q < 10; q++)
        ((ulonglong2*)(g_hbias + g * 20))[q] = make_ulonglong2(hb[2 * q], hb[2 * q + 1]);
}

// =====================================================================
// Pass 3: xo = ffn([xe, xg], Wo1, Wo2); segment-sum -> g_pooled.  P=2.
// Layer 1 starts from per-graph hbias: only 5 xe inputs remain.
// =====================================================================
__global__ void __launch_bounds__(256, 2) k_out(const int* __restrict__ batch) {
    int tid = threadIdx.x;
    int t = blockIdx.x * 256 + tid;
    int i0 = t * 2;
    if (i0 >= NPTS) return;

    int2 bb = *(const int2*)(batch + i0);
    int bA = bb.x, bB = bb.y;
    bool same = (bA == bB);

    // init hidden accumulators from per-graph bias (broadcast LDG.128, L2-resident)
    u64 hA[20], hB[20];
    {
        const ulonglong2* pA = (const ulonglong2*)(g_hbias + bA * 20);
#pragma unroll
        for (int q = 0; q < 10; q++) {
            ulonglong2 v = pA[q];
            hA[2 * q] = v.x; hA[2 * q + 1] = v.y;
        }
        if (same) {
#pragma unroll
            for (int q = 0; q < 20; q++) hB[q] = hA[q];
        } else {
            const ulonglong2* pB = (const ulonglong2*)(g_hbias + bB * 20);
#pragma unroll
            for (int q = 0; q < 10; q++) {
                ulonglong2 v = pB[q];
                hB[2 * q] = v.x; hB[2 * q + 1] = v.y;
            }
        }
    }

    float inA[5], inB[5];
    {
        const float2* xep = (const float2*)(g_xe + i0 * 5);
        float2 e0 = xep[0], e1 = xep[1], e2 = xep[2], e3 = xep[3], e4 = xep[4];
        inA[0] = e0.x; inA[1] = e0.y; inA[2] = e1.x; inA[3] = e1.y; inA[4] = e2.x;
        inB[0] = e2.y; inB[1] = e3.x; inB[2] = e3.y; inB[3] = e4.x; inB[4] = e4.y;
    }

    // hidden: += W1a·xe (5 inputs only)
#pragma unroll
    for (int k = 0; k < 5; k++) {
        u64 aA = pk2(inA[k], inA[k]);
        u64 aB = pk2(inB[k], inB[k]);
#pragma unroll
        for (int q = 0; q < 20; q++) {
            u64 w = cWo1[k * 20 + q];
            hA[q] = ffma2(aA, w, hA[q]);
            hB[q] = ffma2(aB, w, hB[q]);
        }
    }
#pragma unroll
    for (int q = 0; q < 20; q++) { hA[q] = plrelu2(hA[q]); hB[q] = plrelu2(hB[q]); }

    // segment bookkeeping (once)
    unsigned peers = __match_any_sync(0xffffffffu, bA);
    int lane = tid & 31;
    int hiL = 31 - __clz(peers);
    bool leader = (lane == __ffs(peers) - 1);

    // out 40 -> 32: 4 groups of 8 outputs; packed dot over hidden pairs
#pragma unroll
    for (int grp = 0; grp < 4; grp++) {
        u64 oA[8], oB[8];
#pragma unroll
        for (int jj = 0; jj < 8; jj++) { oA[jj] = 0ULL; oB[jj] = 0ULL; }
#pragma unroll
        for (int q = 0; q < 20; q++) {
            u64 a = hA[q], b = hB[q];
#pragma unroll
            for (int jj = 0; jj < 8; jj++) {
                u64 w = cWo2t[(grp * 8 + jj) * 20 + q];
                oA[jj] = ffma2(a, w, oA[jj]);
                oB[jj] = ffma2(b, w, oB[jj]);
            }
        }
#pragma unroll
        for (int jj = 0; jj < 8; jj++) {
            float lo, hi;
            up2(oA[jj], lo, hi);
            float vA = lrelu(lo + hi);
            up2(oB[jj], lo, hi);
            float vB = lrelu(lo + hi);
            float v = same ? (vA + vB) : vA;
#pragma unroll
            for (int d = 1; d < 32; d <<= 1) {
                float s = __shfl_down_sync(0xffffffffu, v, d);
                if (lane + d <= hiL) v += s;
            }
            int c = grp * 8 + jj;
            if (leader) atomicAdd(&g_pooled[bA * 32 + c], v);
            if (!same)  atomicAdd(&g_pooled[bB * 32 + c], vB);
        }
    }
}

// =====================================================================
// Pass 4: out = ffn(pooled, Wd1, Wd2, final_linear=True)
// =====================================================================
__global__ void __launch_bounds__(256) k_disc(float* __restrict__ out) {
    int g = blockIdx.x * 256 + threadIdx.x;   // grid = NG/256 exactly
    float p[32];
#pragma unroll
    for (int j = 0; j < 32; j++) p[j] = g_pooled[g * 32 + j];

    u64 acc[20];
#pragma unroll
    for (int j = 0; j < 20; j++) acc[j] = 0ULL;
#pragma unroll
    for (int k = 0; k < 32; k++) {
        u64 a = pk2(p[k], p[k]);
#pragma unroll
        for (int q = 0; q < 20; q++) acc[q] = ffma2(a, cWd1[k * 20 + q], acc[q]);
    }
    u64 s = 0ULL;
#pragma unroll
    for (int j = 0; j < 20; j++) s = ffma2(plrelu2(acc[j]), cWd2[j], s);
    float lo, hi; up2(s, lo, hi);
    out[g] = lo + hi;   // final_linear: no activation
}

extern "C" void kernel_launch(void* const* d_in, const int* in_sizes, int n_in,
                              void* d_out, int out_size) {
    const float* x     = (const float*)d_in[0];
    const int*   batch = (const int*)d_in[1];
    float* out = (float*)d_out;

    // Direct-layout weights -> constant (async D2D)
    cudaMemcpyToSymbolAsync(cWe1, d_in[2],  120 * 4, 0, cudaMemcpyDeviceToDevice, 0);
    cudaMemcpyToSymbolAsync(cWg1, d_in[4],  200 * 4, 0, cudaMemcpyDeviceToDevice, 0);
    cudaMemcpyToSymbolAsync(cWg2, d_in[5],  160 * 4, 0, cudaMemcpyDeviceToDevice, 0);
    cudaMemcpyToSymbolAsync(cWo1, d_in[6],  360 * 4, 0, cudaMemcpyDeviceToDevice, 0);
    cudaMemcpyToSymbolAsync(cWd1, d_in[8], 1280 * 4, 0, cudaMemcpyDeviceToDevice, 0);
    cudaMemcpyToSymbolAsync(cWd2, d_in[9],   40 * 4, 0, cudaMemcpyDeviceToDevice, 0);

    // k_pre: zero g_aggr + build transposed packed layer-2 weights, then stage
    k_pre<<<(NG * 5 / 4 + 255) / 256, 256>>>((const float*)d_in[3], (const float*)d_in[7]);
    void* pWe2t = nullptr; void* pWo2t = nullptr;
    cudaGetSymbolAddress(&pWe2t, g_We2t_dev);
    cudaGetSymbolAddress(&pWo2t, g_Wo2t_dev);
    cudaMemcpyToSymbolAsync(cWe2t, pWe2t, 100 * 8, 0, cudaMemcpyDeviceToDevice, 0);
    cudaMemcpyToSymbolAsync(cWo2t, pWo2t, 640 * 8, 0, cudaMemcpyDeviceToDevice, 0);

    const int nblk2 = (NPTS / 2 + 255) / 256;   // P=2 kernels
    k_emb<<<nblk2, 256>>>(x, batch);
    k_glob<<<NG / 256, 256>>>();
    k_out<<<nblk2, 256>>>(batch);
    k_disc<<<NG / 256, 256>>>(out);
}